// round 17
// baseline (speedup 1.0000x reference)
#include <cuda_runtime.h>
#include <cuda_bf16.h>
#define MB 128
#define KS 64
#define NST 5
#define TT 6
#define AST 132
#define PLROW 272
#define PLB 34816
#define ALO 17408
typedef unsigned long long u64; typedef unsigned int u32;

__device__ __align__(16) char g_W[12*PLB]; // planes 2L=hi,2L+1=lo; L:0 Wq_a 1 Wq_b 2 Wq_self 3 W2a 4 W2b 5 W3; [n][k] bf16 stride 272B
__device__ float g_bq[384], g_b2[128], g_b3[128];

__device__ __forceinline__ u64 pk2(float a,float b){u64 d;asm("mov.b64 %0,{%1,%2};":"=l"(d):"f"(a),"f"(b));return d;}
__device__ __forceinline__ void upk2(u64 v,float&a,float&b){asm("mov.b64 {%0,%1},%2;":"=f"(a),"=f"(b):"l"(v));}
__device__ __forceinline__ u64 fma2(u64 a,u64 b,u64 c){u64 d;asm("fma.rn.f32x2 %0,%1,%2,%3;":"=l"(d):"l"(a),"l"(b),"l"(c));return d;}
__device__ __forceinline__ u64 add2(u64 a,u64 b){u64 d;asm("add.rn.f32x2 %0,%1,%2;":"=l"(d):"l"(a),"l"(b));return d;}

// ---------------- prep ----------------
__device__ __forceinline__ void wput(int L,int k,int n,float v){
    __nv_bfloat16 h=__float2bfloat16_rn(v);
    __nv_bfloat16 lo=__float2bfloat16_rn(v-__bfloat162float(h));
    u32 off=(u32)n*PLROW+(u32)k*2;
    *(__nv_bfloat16*)(g_W+(2*L)*PLB+off)=h;
    *(__nv_bfloat16*)(g_W+(2*L+1)*PLB+off)=lo;
}
__device__ __forceinline__ float wc1(int k,int c,const float* s1,const float* i1){
    if(c<128)return s1[k*128+c]; if(c<256)return i1[k*128+c-128]; return i1[(128+k)*128+c-256];
}
#define PBF 128
#define PBQ 512
#define PBB 513
#define PBT 514
#define PBN (514+854)
__global__ __launch_bounds__(384) void prep(const float* gt,const float* ew2,const float* eb2,
    const float* sw1,const float* sb1,const float* sw2,const float* sb2,const float* iw1,
    const float* iw2,const float* ib2,const float* uw1,const float* ub1,const float* uw2,
    const float* ub2,const float* dw1,const float* db1,float* out){
    int bid=blockIdx.x,tx=threadIdx.x;
    __shared__ float ar[128];
    if(bid<PBF){
        int k=bid; if(tx<128)ar[tx]=ew2[k*128+tx]; __syncthreads();
        float a=0.f;
        #pragma unroll 8
        for(int q=0;q<128;q++)a+=ar[q]*wc1(q,tx,sw1,iw1);
        int sl=tx>>7; int L=(sl==0)?2:(sl==1)?0:1;
        wput(L,k,tx&127,a);
    } else if(bid<PBQ){
        int wh=(bid-PBF)>>7,k=(bid-PBF)&127; const float*A,*Bm;
        if(wh==0){A=sw2;Bm=uw1;}else if(wh==1){A=iw2;Bm=uw1+16384;}else{A=uw2;Bm=dw1;}
        if(tx<128)ar[tx]=A[k*128+tx]; __syncthreads();
        if(tx<128){float a=0.f;
            #pragma unroll 16
            for(int q=0;q<128;q++)a+=ar[q]*Bm[q*128+tx];
            wput(3+wh,k,tx,a);}
    } else if(bid==PBQ){
        if(tx<128)ar[tx]=eb2[tx]; __syncthreads();
        float a=(tx<128)?sb1[tx]:0.f;
        #pragma unroll 16
        for(int q=0;q<128;q++)a+=ar[q]*wc1(q,tx,sw1,iw1);
        g_bq[tx]=a;
    } else if(bid==PBB){
        if(tx<128){float a2=ub1[tx],a3=db1[tx];
            #pragma unroll 16
            for(int q=0;q<128;q++){a2+=sb2[q]*uw1[q*128+tx]+ib2[q]*uw1[(128+q)*128+tx];a3+=ub2[q]*dw1[q*128+tx];}
            g_b2[tx]=a2;g_b3[tx]=a3;}
    } else {
        int o=(bid-PBT)*384+tx;
        if(o<MB*NST*KS*8){int b=o/(NST*KS*8),r=o%(NST*KS*8),t=r/(KS*8),kd=r%(KS*8);
            out[MB*NST*KS*8+o]=gt[b*(TT*KS*8)+(t+1)*(KS*8)+kd];}
    }
}

// ---------------- mma/ldmatrix ----------------
__device__ __forceinline__ void ldsm4(u32* r,u32 a){
    asm volatile("ldmatrix.sync.aligned.m8n8.x4.shared.b16 {%0,%1,%2,%3},[%4];"
        :"=r"(r[0]),"=r"(r[1]),"=r"(r[2]),"=r"(r[3]):"r"(a));
}
__device__ __forceinline__ void mmab(float* d,const u32* a,u32 b0,u32 b1){
    asm volatile("mma.sync.aligned.m16n8k16.row.col.f32.bf16.bf16.f32 "
        "{%0,%1,%2,%3},{%4,%5,%6,%7},{%8,%9},{%0,%1,%2,%3};"
        :"+f"(d[0]),"+f"(d[1]),"+f"(d[2]),"+f"(d[3])
        :"r"(a[0]),"r"(a[1]),"r"(a[2]),"r"(a[3]),"r"(b0),"r"(b1));
}
// D += A(aS bf16 hi plane; +ALO lo) @ W(wS plane); dual: (Ahi+Alo)*W else Ahi*W
__device__ __noinline__ void gpass(float (*d)[4],u32 aS,u32 wS,int dual,int wid,int lane){
    const int rb=(wid&3)*16, cb=(wid>>2)*64;
    const u32 aad=aS+(u32)(rb+(lane&7)+((lane>>3)&1)*8)*PLROW+((lane>>4)&1)*16;
    const u32 wad=wS+(u32)(cb+((lane>>4)&1)*8+(lane&7))*PLROW+((lane>>3)&1)*16;
    #pragma unroll 2
    for(int kst=0;kst<8;kst++){
        u32 ah[4],al[4];
        ldsm4(ah,aad+kst*32);
        if(dual)ldsm4(al,aad+ALO+kst*32);
        #pragma unroll
        for(int p=0;p<4;p++){
            u32 bw[4];
            ldsm4(bw,wad+(u32)p*16*PLROW+kst*32);
            mmab(d[2*p],ah,bw[0],bw[1]); mmab(d[2*p+1],ah,bw[2],bw[3]);
            if(dual){mmab(d[2*p],al,bw[0],bw[1]); mmab(d[2*p+1],al,bw[2],bw[3]);}
        }
    }
}
__device__ __forceinline__ void ginit(float (*d)[4]){
    #pragma unroll
    for(int i=0;i<8;i++){d[i][0]=0.f;d[i][1]=0.f;d[i][2]=0.f;d[i][3]=0.f;}
}
// D -> fp32 tile [64][AST]
__device__ __forceinline__ void epiS(float (*d)[4],const float* bias,float* dst,int relu,int wid,int lane){
    int r0=(wid&3)*16+(lane>>2), cbase=(wid>>2)*64+2*(lane&3);
    #pragma unroll
    for(int nt=0;nt<8;nt++){
        int c0=cbase+nt*8; float b0=bias[c0],b1=bias[c0+1];
        float v00=d[nt][0]+b0,v01=d[nt][1]+b1,v10=d[nt][2]+b0,v11=d[nt][3]+b1;
        if(relu){v00=fmaxf(v00,0.f);v01=fmaxf(v01,0.f);v10=fmaxf(v10,0.f);v11=fmaxf(v11,0.f);}
        *(float2*)(dst+r0*AST+c0)=make_float2(v00,v01);
        *(float2*)(dst+(r0+8)*AST+c0)=make_float2(v10,v11);
    }
}
// D -> bf16 hi/lo planes
__device__ __forceinline__ void epiB(float (*d)[4],const float* bias,char* pl,int relu,int wid,int lane){
    int r0=(wid&3)*16+(lane>>2), cbase=(wid>>2)*64+2*(lane&3);
    #pragma unroll
    for(int nt=0;nt<8;nt++){
        int c0=cbase+nt*8; float b0=bias[c0],b1=bias[c0+1];
        float v[4]={d[nt][0]+b0,d[nt][1]+b1,d[nt][2]+b0,d[nt][3]+b1};
        if(relu){v[0]=fmaxf(v[0],0.f);v[1]=fmaxf(v[1],0.f);v[2]=fmaxf(v[2],0.f);v[3]=fmaxf(v[3],0.f);}
        #pragma unroll
        for(int h=0;h<2;h++){
            int row=r0+h*8;
            __nv_bfloat162 hi=__floats2bfloat162_rn(v[2*h],v[2*h+1]);
            __nv_bfloat162 lo=__floats2bfloat162_rn(v[2*h]-__bfloat162float(hi.x),v[2*h+1]-__bfloat162float(hi.y));
            *(u32*)(pl+row*PLROW+c0*2)=*(u32*)&hi;
            *(u32*)(pl+ALO+row*PLROW+c0*2)=*(u32*)&lo;
        }
    }
}
// fp32 tile -> bf16 planes
__device__ __forceinline__ void splitT(const float* src,char* pl,int tx){
    int row=tx>>2,c0=(tx&3)*32;
    #pragma unroll
    for(int i=0;i<16;i++){
        float2 v=*(const float2*)(src+row*AST+c0+2*i);
        __nv_bfloat162 hi=__floats2bfloat162_rn(v.x,v.y);
        __nv_bfloat162 lo=__floats2bfloat162_rn(v.x-__bfloat162float(hi.x),v.y-__bfloat162float(hi.y));
        *(u32*)(pl+row*PLROW+(c0+2*i)*2)=*(u32*)&hi;
        *(u32*)(pl+ALO+row*PLROW+(c0+2*i)*2)=*(u32*)&lo;
    }
}
// He = relu(pred@We1+eb1) -> bf16 planes
__device__ __forceinline__ void encp(const float* sP,const float* sWe1,const float* sE1,char* pl,int tx){
    int row=tx>>2,c0=(tx&3)*32;
    float o[32];
    #pragma unroll
    for(int i=0;i<32;i++)o[i]=sE1[c0+i];
    #pragma unroll
    for(int k=0;k<8;k++){float p=sP[row*8+k];
        #pragma unroll
        for(int i=0;i<32;i++)o[i]+=p*sWe1[k*128+c0+i];}
    #pragma unroll
    for(int i=0;i<16;i++){
        float a=fmaxf(o[2*i],0.f),b=fmaxf(o[2*i+1],0.f);
        __nv_bfloat162 hi=__floats2bfloat162_rn(a,b);
        __nv_bfloat162 lo=__floats2bfloat162_rn(a-__bfloat162float(hi.x),b-__bfloat162float(hi.y));
        *(u32*)(pl+row*PLROW+(c0+2*i)*2)=*(u32*)&hi;
        *(u32*)(pl+ALO+row*PLROW+(c0+2*i)*2)=*(u32*)&lo;
    }
}
// pairwise fp32, in place on sB (R11-proven)
__device__ void pw(const float* sA,float* sB,const float* sI1,int tx){
    int hp=tx&63,jg=tx>>6;
    const float* ab=sA+hp*2;
    float* bb=sB+jg*16*AST+hp*2;
    u64 bi=*(const u64*)(sI1+hp*2);
    u64 vj[16],ac[16];
    #pragma unroll
    for(int t=0;t<16;t++){vj[t]=add2(*(const u64*)(bb+t*AST),bi);ac[t]=0ULL;}
    u64 Sa=0ULL; const u64 M=0x7FFFFFFF7FFFFFFFULL;
    #pragma unroll 1
    for(int c=0;c<8;c++){u64 ap[8];
        #pragma unroll
        for(int i=0;i<8;i++){ap[i]=*(const u64*)(ab+(c*8+i)*AST);Sa=add2(Sa,ap[i]);}
        #pragma unroll
        for(int t=0;t<16;t++){u64 v=vj[t],s=ac[t];
            #pragma unroll
            for(int i=0;i<8;i++){u64 x=add2(ap[i],v);x&=M;s=add2(s,x);}
            ac[t]=s;}}
    #pragma unroll
    for(int t=0;t<16;t++){float sl,sh,al,ah,vl,vh;
        upk2(ac[t],sl,sh);upk2(Sa,al,ah);upk2(vj[t],vl,vh);
        *(u64*)(bb+t*AST)=pk2((al+64.f*vl+sl)*(0.5f/64.f),(ah+64.f*vh+sh)*(0.5f/64.f));}
}
__device__ __forceinline__ void decf(const float* sHd,const float* sWdp,const float* sD2,float* sP,float* out,int b,int step,int tx){
    int m=tx>>2,d0=(tx&3)*2;
    const float* hp=sHd+m*AST; u64 a0=0,a1=0;
    const float* w0=sWdp+d0*2; const float* w1=sWdp+(d0+1)*2;
    #pragma unroll 8
    for(int k=0;k<64;k++){u64 h2=*(const u64*)(hp+2*k);
        a0=fma2(h2,*(const u64*)(w0+k*16),a0); a1=fma2(h2,*(const u64*)(w1+k*16),a1);}
    float lo,hi; upk2(a0,lo,hi); float v0=lo+hi+sD2[d0];
    upk2(a1,lo,hi); float v1=lo+hi+sD2[d0+1];
    sP[m*8+d0]=v0; sP[m*8+d0+1]=v1;
    *(float2*)(out+((b*NST+step)*KS+m)*8+d0)=make_float2(v0,v1);
}
// ---------------- ring ----------------
__device__ __forceinline__ void kick(u32 dstS,const char* src,int tx){
    #pragma unroll
    for(int t=0;t<9;t++){int lin=t*256+tx;
        if(lin<PLB/16)
            asm volatile("cp.async.cg.shared.global [%0],[%1],16;"::"r"(dstS+(u32)lin*16),"l"(src+lin*16):"memory");}
    asm volatile("cp.async.commit_group;":::"memory");
}
__device__ __forceinline__ u32 pipe_adv(u32 ringS,int& ph,int& slot,int tx){
    asm volatile("cp.async.wait_group 1;":::"memory");
    __syncthreads();
    int nh=ph+2; if(nh>=12)nh-=12;
    kick(ringS+(u32)((slot+2)%3)*PLB,g_W+nh*PLB,tx);
    u32 cur=ringS+(u32)slot*PLB;
    ph=(ph+1==12)?0:ph+1; slot=(slot+1)%3;
    return cur;
}
// ---------------- smem map ----------------
#define O_HE 104448
#define O_R1 139264
#define O_R2 174080
#define O_SP 208896
#define O_WE 210944
#define O_WD 215040
#define O_BQ 219136
#define O_B2 220672
#define O_B3 221184
#define O_E1 221696
#define O_I1 222208
#define O_D2 222720
#define SMB  222752

__global__ __launch_bounds__(256,1) void rollout(const float* gt,const float* we1,const float* eb1,
        const float* ib1,const float* wd,const float* db2,float* out){
    extern __shared__ __align__(16) char smc[];
    u32 S=(u32)__cvta_generic_to_shared(smc);
    float* sP=(float*)(smc+O_SP); float* sWe1=(float*)(smc+O_WE); float* sWdp=(float*)(smc+O_WD);
    float* sBQ=(float*)(smc+O_BQ); float* sB2=(float*)(smc+O_B2); float* sB3=(float*)(smc+O_B3);
    float* sE1=(float*)(smc+O_E1); float* sI1=(float*)(smc+O_I1); float* sD2=(float*)(smc+O_D2);
    float* r1f=(float*)(smc+O_R1); float* r2f=(float*)(smc+O_R2);
    const int tx=threadIdx.x,wid=tx>>5,lane=tx&31,b=blockIdx.x;

    #pragma unroll
    for(int t=0;t<4;t++){int i=t*256+tx; sWe1[i]=we1[i]; int k=i>>3,d=i&7; sWdp[(k>>1)*16+d*2+(k&1)]=wd[i];}
    if(tx<128){sBQ[tx]=g_bq[tx];sBQ[128+tx]=g_bq[128+tx];sBQ[256+tx]=g_bq[256+tx];
        sB2[tx]=g_b2[tx];sB3[tx]=g_b3[tx];sE1[tx]=eb1[tx];sI1[tx]=ib1[tx];}
    if(tx<8)sD2[tx]=db2[tx];
    sP[tx]=gt[b*(TT*KS*8)+tx]; sP[256+tx]=gt[b*(TT*KS*8)+256+tx];
    __syncthreads();
    encp(sP,sWe1,sE1,smc+O_HE,tx);
    int ph=0,slot=0;
    kick(S,g_W,tx); kick(S+PLB,g_W+PLB,tx);
    float d[8][4];
    #pragma unroll 1
    for(int step=0;step<NST;step++){
        u32 w;
        // a = He@Wq_a
        ginit(d);
        w=pipe_adv(S,ph,slot,tx); gpass(d,S+O_HE,w,1,wid,lane);
        w=pipe_adv(S,ph,slot,tx); gpass(d,S+O_HE,w,0,wid,lane);
        epiS(d,sBQ+128,r1f,0,wid,lane);
        // b = He@Wq_b
        ginit(d);
        w=pipe_adv(S,ph,slot,tx); gpass(d,S+O_HE,w,1,wid,lane);
        w=pipe_adv(S,ph,slot,tx); gpass(d,S+O_HE,w,0,wid,lane);
        epiS(d,sBQ+256,r2f,0,wid,lane);
        __syncthreads();
        pw(r1f,r2f,sI1,tx);
        __syncthreads();
        splitT(r2f,smc+O_R1,tx);                 // r -> bf16 planes (region1)
        // Hself = relu(He@Wq_self)
        ginit(d);
        w=pipe_adv(S,ph,slot,tx); gpass(d,S+O_HE,w,1,wid,lane);
        w=pipe_adv(S,ph,slot,tx); gpass(d,S+O_HE,w,0,wid,lane);
        epiB(d,sBQ,smc+O_R2,1,wid,lane);         // Hself -> region2 planes
        // Hu = relu(Hself@W2a + r@W2b + b2)
        ginit(d);
        w=pipe_adv(S,ph,slot,tx); gpass(d,S+O_R2,w,1,wid,lane);
        w=pipe_adv(S,ph,slot,tx); gpass(d,S+O_R2,w,0,wid,lane);
        w=pipe_adv(S,ph,slot,tx); gpass(d,S+O_R1,w,1,wid,lane);
        w=pipe_adv(S,ph,slot,tx); gpass(d,S+O_R1,w,0,wid,lane);
        epiB(d,sB2,smc+O_HE,1,wid,lane);         // Hu -> He region planes
        // Hd = relu(Hu@W3 + b3)
        ginit(d);
        w=pipe_adv(S,ph,slot,tx); gpass(d,S+O_HE,w,1,wid,lane);
        w=pipe_adv(S,ph,slot,tx); gpass(d,S+O_HE,w,0,wid,lane);
        epiS(d,sB3,r1f,1,wid,lane);
        __syncthreads();
        decf(r1f,sWdp,sD2,sP,out,b,step,tx);
        __syncthreads();
        encp(sP,sWe1,sE1,smc+O_HE,tx);           // He' planes
    }
    asm volatile("cp.async.wait_group 0;":::"memory");
}

extern "C" void kernel_launch(void* const* d_in,const int* in_sizes,int n_in,void* d_out,int out_size){
    const float* gt=(const float*)d_in[0];
    const float* enc_w1=(const float*)d_in[2];  const float* enc_b1=(const float*)d_in[3];
    const float* enc_w2=(const float*)d_in[4];  const float* enc_b2=(const float*)d_in[5];
    const float* self_w1=(const float*)d_in[6]; const float* self_b1=(const float*)d_in[7];
    const float* self_w2=(const float*)d_in[8]; const float* self_b2=(const float*)d_in[9];
    const float* inter_w1=(const float*)d_in[10];const float* inter_b1=(const float*)d_in[11];
    const float* inter_w2=(const float*)d_in[12];const float* inter_b2=(const float*)d_in[13];
    const float* upd_w1=(const float*)d_in[14]; const float* upd_b1=(const float*)d_in[15];
    const float* upd_w2=(const float*)d_in[16]; const float* upd_b2=(const float*)d_in[17];
    const float* dec_w1=(const float*)d_in[18]; const float* dec_b1=(const float*)d_in[19];
    const float* dec_w2=(const float*)d_in[20]; const float* dec_b2=(const float*)d_in[21];
    float* out=(float*)d_out;
    cudaFuncSetAttribute(rollout,cudaFuncAttributeMaxDynamicSharedMemorySize,SMB);
    prep<<<PBN,384>>>(gt,enc_w2,enc_b2,self_w1,self_b1,self_w2,self_b2,inter_w1,
                      inter_w2,inter_b2,upd_w1,upd_b1,upd_w2,upd_b2,dec_w1,dec_b1,out);
    rollout<<<MB,256,SMB>>>(gt,enc_w1,enc_b1,inter_b1,dec_w2,dec_b2,out);
}